// round 14
// baseline (speedup 1.0000x reference)
#include <cuda_runtime.h>

#define BATCH 16
#define H 256
#define W 256
#define HW (H*W)
#define NPLANE 12            // unique off-center taps (center weight == 1)
#define RAD 2
#define NITER 10
#define GB 8                 // batches per phase (L2 working set ~51.5 MB)

// padded weight plane: 2 cols left, 2 cols right, 2 rows bottom (zeros)
#define PW 260
#define PH 258
#define PLANE (PW*PH)

// mf_iter tile: 256 threads, 2 adjacent px/thread -> 64x8 pixels
#define NT 256
#define TILEW 64
#define TH 8
#define SHW (TILEW + 2*RAD)   // 68
#define SHH (TH + 2*RAD)      // 12

// build tile: 32x8 px
#define BTW 32
#define BHALOW (BTW + 2*RAD)  // 36
#define BHALOH (TH + 2*RAD)   // 12

// Scratch (no cudaMalloc): ~137 MB of __device__ globals.
__device__ float2 g_k[BATCH * NPLANE * PLANE];  // interleaved {kA,kB}, padded
__device__ float4 g_L[2][BATCH * HW];           // {logxA, log1mxA, logxB, log1mxB}
__device__ unsigned int g_cnt[BATCH * 8];

// ---------------------------------------------------------------------------
__global__ __launch_bounds__(256) void zero_pad() {
    float2* p = g_k + (size_t)blockIdx.x * PLANE;
    const float2 z = make_float2(0.f, 0.f);
    for (int i = threadIdx.x; i < 2 * PW; i += 256) {
        int r = 256 + i / PW, c = i % PW;
        p[r * PW + c] = z;
    }
    for (int i = threadIdx.x; i < 256 * 4; i += 256) {
        int r = i / 4, cc = i % 4;
        int c = (cc < 2) ? cc : (256 + cc);
        p[r * PW + c] = z;
    }
    if (blockIdx.x == 0 && threadIdx.x < BATCH * 8)
        g_cnt[threadIdx.x] = 0u;
}

// ---------------------------------------------------------------------------
// Build 12 unique-tap weight plane pairs per batch; fused mean-field init.
// ---------------------------------------------------------------------------
__global__ __launch_bounds__(256) void build_kernels(
    const float* __restrict__ fm, const float* __restrict__ depth,
    const float* __restrict__ seg) {
    __shared__ float sf0[BHALOH][BHALOW];
    __shared__ float sf1[BHALOH][BHALOW];
    __shared__ float sf2[BHALOH][BHALOW];
    __shared__ float sd [BHALOH][BHALOW];

    int b   = blockIdx.z;
    int ty0 = blockIdx.y * TH;
    int tx0 = blockIdx.x * BTW;
    int tid = threadIdx.y * BTW + threadIdx.x;

    for (int i = tid; i < BHALOH * BHALOW; i += TH * BTW) {
        int hy = i / BHALOW, hx = i % BHALOW;
        int gy = ty0 + hy - RAD, gx = tx0 + hx - RAD;
        float f0 = 0.f, f1 = 0.f, f2 = 0.f, d = 0.f;
        if (gy >= 0 && gy < H && gx >= 0 && gx < W) {
            int idx = gy * W + gx;
            f0 = fm[(b * 3 + 0) * HW + idx] + 10.f;
            f1 = fm[(b * 3 + 1) * HW + idx] + 10.f;
            f2 = fm[(b * 3 + 2) * HW + idx] + 10.f;
            d  = depth[b * HW + idx];
        }
        sf0[hy][hx] = f0; sf1[hy][hx] = f1; sf2[hy][hx] = f2; sd[hy][hx] = d;
    }
    __syncthreads();

    int ly = threadIdx.y, lx = threadIdx.x;
    int gy = ty0 + ly, gx = tx0 + lx;

    float c0 = sf0[ly + RAD][lx + RAD];
    float c1 = sf1[ly + RAD][lx + RAD];
    float c2 = sf2[ly + RAD][lx + RAD];
    float cd = sd [ly + RAD][lx + RAD];

    float2* kout = g_k + (size_t)(b * NPLANE) * PLANE + gy * PW + (gx + 2);

    #pragma unroll
    for (int t = 0; t < NPLANE; t++) {
        int kh = t / 5, kw = t % 5;
        float d0 = sf0[ly + kh][lx + kw] - c0;
        float d1 = sf1[ly + kh][lx + kw] - c1;
        float d2 = sf2[ly + kh][lx + kw] - c2;
        float s  = d0 * d0 + d1 * d1 + d2 * d2;
        float k  = expf(-(s / 0.02f));
        float dd = sd[ly + kh][lx + kw] - cd;
        float ks = k * expf(-((dd * dd) / 0.02f));
        kout[(size_t)t * PLANE] = make_float2(k, ks);
    }

    // fused mean-field init: x0 = clip(seg, 0.1, 0.9); store log pair x2
    {
        int idx = b * HW + gy * W + gx;
        float x = fminf(fmaxf(seg[idx], 0.1f), 0.9f);
        float l1 = logf(x), l0 = logf(1.0f - x);
        g_L[0][idx] = make_float4(l1, l0, l1, l0);
    }
}

// ---------------------------------------------------------------------------
__device__ __forceinline__ float4 ldg_wm_odd(const float2* p) {
    float2 a = __ldg(p);
    float2 bb = __ldg(p + 1);
    return make_float4(a.x, a.y, bb.x, bb.y);
}

#define S4(arr, r, c) (*(const float4*)&arr[r][c])

// per-tap FMA block: EXACT round-8 statement shapes and order per accumulator
#define ACC(wf, wm, fA0x,fA0y, fA1x,fA1y, fB0x,fB0y, fB1x,fB1y, \
                 mA0x,mA0y, mA1x,mA1y, mB0x,mB0y, mB1x,mB1y)    \
    S1A0 += wf.x*fA0x + wm.x*mA0x;                              \
    S0A0 += wf.x*fA0y + wm.x*mA0y;                              \
    S1B0 += wf.y*fB0x + wm.y*mB0x;                              \
    S0B0 += wf.y*fB0y + wm.y*mB0y;                              \
    S1A1 += wf.z*fA1x + wm.z*mA1x;                              \
    S0A1 += wf.z*fA1y + wm.z*mA1y;                              \
    S1B1 += wf.w*fB1x + wm.w*mB1x;                              \
    S0B1 += wf.w*fB1y + wm.w*mB1y;

// ---------------------------------------------------------------------------
// One mean-field iteration, 2 adjacent px/thread, per-chain float2 smem.
// Tap order and FMA sequence per pixel identical to rounds 8-13 (bitwise-
// preserving); only load widths changed (float4 weight pairs, float4 smem
// staging covering 2 px of one chain).
// ---------------------------------------------------------------------------
__global__ __launch_bounds__(NT, 4) void mf_iter(
    int src, int last, int b0,
    const float* __restrict__ seg, const float* __restrict__ targets,
    const float* __restrict__ sam, float* __restrict__ out_mask) {
    __shared__ float2 sA[SHH][SHW];   // {logx, log1mx} chain A
    __shared__ float2 sB[SHH][SHW];   // chain B

    int b   = b0 + blockIdx.z;
    int ty0 = blockIdx.y * TH;
    int tx0 = blockIdx.x * TILEW;
    int tid = threadIdx.x;

    const float4* __restrict__ Ls = g_L[src];
    float4* Ld = g_L[src ^ 1];

    for (int i = tid; i < SHH * SHW; i += NT) {
        int hy = i / SHW, hx = i % SHW;
        int gy = ty0 + hy - RAD, gx = tx0 + hx - RAD;
        float4 v = make_float4(0.f, 0.f, 0.f, 0.f);
        if ((unsigned)gy < H && (unsigned)gx < W)
            v = __ldcs(&Ls[b * HW + gy * W + gx]);
        sA[hy][hx] = make_float2(v.x, v.y);
        sB[hy][hx] = make_float2(v.z, v.w);
    }
    __syncthreads();

    int lx = tid & 31;                // 0..31
    int ly = tid >> 5;                // 0..7
    int C  = 2 * lx;                  // tile-local col of px0 (even)
    int gy = ty0 + ly, gx = tx0 + C;  // px1 at gx+1

    const float2* __restrict__ kp =
        g_k + (size_t)(b * NPLANE) * PLANE + gy * PW + (gx + 2);

    float S1A0=0.f,S0A0=0.f,S1B0=0.f,S0B0=0.f;
    float S1A1=0.f,S0A1=0.f,S1B1=0.f,S0B1=0.f;

    // ---- Chunk A: t=0,1,2 (kh=0; fwd row ly, mirror row ly+4) ----
    {
        float4 fa0 = S4(sA, ly+0, C),   fa1 = S4(sA, ly+0, C+2);
        float4 fb0 = S4(sB, ly+0, C),   fb1 = S4(sB, ly+0, C+2);
        float4 ma0 = S4(sA, ly+4, C+2), ma1 = S4(sA, ly+4, C+4);
        float4 mb0 = S4(sB, ly+4, C+2), mb1 = S4(sB, ly+4, C+4);
        { // t=0 kw=0: f cols 0,1 ; m cols 4,5 ; moff=522
            float4 wf = __ldg((const float4*)(kp));
            float4 wm = __ldg((const float4*)(kp + 522));
            ACC(wf, wm, fa0.x,fa0.y, fa0.z,fa0.w, fb0.x,fb0.y, fb0.z,fb0.w,
                        ma1.x,ma1.y, ma1.z,ma1.w, mb1.x,mb1.y, mb1.z,mb1.w)
        }
        { // t=1 kw=1: f cols 1,2 ; m cols 3,4 ; moff=521 (odd)
            float4 wf = __ldg((const float4*)(kp + (size_t)1*PLANE));
            float4 wm = ldg_wm_odd(kp + (size_t)1*PLANE + 521);
            ACC(wf, wm, fa0.z,fa0.w, fa1.x,fa1.y, fb0.z,fb0.w, fb1.x,fb1.y,
                        ma0.z,ma0.w, ma1.x,ma1.y, mb0.z,mb0.w, mb1.x,mb1.y)
        }
        { // t=2 kw=2: f cols 2,3 ; m cols 2,3 ; moff=520
            float4 wf = __ldg((const float4*)(kp + (size_t)2*PLANE));
            float4 wm = __ldg((const float4*)(kp + (size_t)2*PLANE + 520));
            ACC(wf, wm, fa1.x,fa1.y, fa1.z,fa1.w, fb1.x,fb1.y, fb1.z,fb1.w,
                        ma0.x,ma0.y, ma0.z,ma0.w, mb0.x,mb0.y, mb0.z,mb0.w)
        }
    }
    // ---- Chunk B: t=3,4 (kh=0) ----
    {
        float4 fa1 = S4(sA, ly+0, C+2), fa2 = S4(sA, ly+0, C+4);
        float4 fb1 = S4(sB, ly+0, C+2), fb2 = S4(sB, ly+0, C+4);
        float4 ma0 = S4(sA, ly+4, C),   ma1 = S4(sA, ly+4, C+2);
        float4 mb0 = S4(sB, ly+4, C),   mb1 = S4(sB, ly+4, C+2);
        { // t=3 kw=3: f cols 3,4 ; m cols 1,2 ; moff=519 (odd)
            float4 wf = __ldg((const float4*)(kp + (size_t)3*PLANE));
            float4 wm = ldg_wm_odd(kp + (size_t)3*PLANE + 519);
            ACC(wf, wm, fa1.z,fa1.w, fa2.x,fa2.y, fb1.z,fb1.w, fb2.x,fb2.y,
                        ma0.z,ma0.w, ma1.x,ma1.y, mb0.z,mb0.w, mb1.x,mb1.y)
        }
        { // t=4 kw=4: f cols 4,5 ; m cols 0,1 ; moff=518
            float4 wf = __ldg((const float4*)(kp + (size_t)4*PLANE));
            float4 wm = __ldg((const float4*)(kp + (size_t)4*PLANE + 518));
            ACC(wf, wm, fa2.x,fa2.y, fa2.z,fa2.w, fb2.x,fb2.y, fb2.z,fb2.w,
                        ma0.x,ma0.y, ma0.z,ma0.w, mb0.x,mb0.y, mb0.z,mb0.w)
        }
    }
    // ---- Chunk C: t=5,6,7 (kh=1; fwd row ly+1, mirror row ly+3) ----
    {
        float4 fa0 = S4(sA, ly+1, C),   fa1 = S4(sA, ly+1, C+2);
        float4 fb0 = S4(sB, ly+1, C),   fb1 = S4(sB, ly+1, C+2);
        float4 ma0 = S4(sA, ly+3, C+2), ma1 = S4(sA, ly+3, C+4);
        float4 mb0 = S4(sB, ly+3, C+2), mb1 = S4(sB, ly+3, C+4);
        { // t=5 kw=0: moff=262
            float4 wf = __ldg((const float4*)(kp + (size_t)5*PLANE));
            float4 wm = __ldg((const float4*)(kp + (size_t)5*PLANE + 262));
            ACC(wf, wm, fa0.x,fa0.y, fa0.z,fa0.w, fb0.x,fb0.y, fb0.z,fb0.w,
                        ma1.x,ma1.y, ma1.z,ma1.w, mb1.x,mb1.y, mb1.z,mb1.w)
        }
        { // t=6 kw=1: moff=261 (odd)
            float4 wf = __ldg((const float4*)(kp + (size_t)6*PLANE));
            float4 wm = ldg_wm_odd(kp + (size_t)6*PLANE + 261);
            ACC(wf, wm, fa0.z,fa0.w, fa1.x,fa1.y, fb0.z,fb0.w, fb1.x,fb1.y,
                        ma0.z,ma0.w, ma1.x,ma1.y, mb0.z,mb0.w, mb1.x,mb1.y)
        }
        { // t=7 kw=2: moff=260
            float4 wf = __ldg((const float4*)(kp + (size_t)7*PLANE));
            float4 wm = __ldg((const float4*)(kp + (size_t)7*PLANE + 260));
            ACC(wf, wm, fa1.x,fa1.y, fa1.z,fa1.w, fb1.x,fb1.y, fb1.z,fb1.w,
                        ma0.x,ma0.y, ma0.z,ma0.w, mb0.x,mb0.y, mb0.z,mb0.w)
        }
    }
    // ---- Chunk D: t=8,9 (kh=1) ----
    {
        float4 fa1 = S4(sA, ly+1, C+2), fa2 = S4(sA, ly+1, C+4);
        float4 fb1 = S4(sB, ly+1, C+2), fb2 = S4(sB, ly+1, C+4);
        float4 ma0 = S4(sA, ly+3, C),   ma1 = S4(sA, ly+3, C+2);
        float4 mb0 = S4(sB, ly+3, C),   mb1 = S4(sB, ly+3, C+2);
        { // t=8 kw=3: moff=259 (odd)
            float4 wf = __ldg((const float4*)(kp + (size_t)8*PLANE));
            float4 wm = ldg_wm_odd(kp + (size_t)8*PLANE + 259);
            ACC(wf, wm, fa1.z,fa1.w, fa2.x,fa2.y, fb1.z,fb1.w, fb2.x,fb2.y,
                        ma0.z,ma0.w, ma1.x,ma1.y, mb0.z,mb0.w, mb1.x,mb1.y)
        }
        { // t=9 kw=4: moff=258
            float4 wf = __ldg((const float4*)(kp + (size_t)9*PLANE));
            float4 wm = __ldg((const float4*)(kp + (size_t)9*PLANE + 258));
            ACC(wf, wm, fa2.x,fa2.y, fa2.z,fa2.w, fb2.x,fb2.y, fb2.z,fb2.w,
                        ma0.x,ma0.y, ma0.z,ma0.w, mb0.x,mb0.y, mb0.z,mb0.w)
        }
    }
    // ---- Chunk E: t=10,11 + center (kh=2; row ly+2 both) ----
    {
        float4 qa0 = S4(sA, ly+2, C), qa1 = S4(sA, ly+2, C+2), qa2 = S4(sA, ly+2, C+4);
        float4 qb0 = S4(sB, ly+2, C), qb1 = S4(sB, ly+2, C+2), qb2 = S4(sB, ly+2, C+4);
        { // t=10 kw=0: f cols 0,1 ; m cols 4,5 ; moff=2
            float4 wf = __ldg((const float4*)(kp + (size_t)10*PLANE));
            float4 wm = __ldg((const float4*)(kp + (size_t)10*PLANE + 2));
            ACC(wf, wm, qa0.x,qa0.y, qa0.z,qa0.w, qb0.x,qb0.y, qb0.z,qb0.w,
                        qa2.x,qa2.y, qa2.z,qa2.w, qb2.x,qb2.y, qb2.z,qb2.w)
        }
        { // t=11 kw=1: f cols 1,2 ; m cols 3,4 ; moff=1 (odd)
            float4 wf = __ldg((const float4*)(kp + (size_t)11*PLANE));
            float4 wm = ldg_wm_odd(kp + (size_t)11*PLANE + 1);
            ACC(wf, wm, qa0.z,qa0.w, qa1.x,qa1.y, qb0.z,qb0.w, qb1.x,qb1.y,
                        qa1.z,qa1.w, qa2.x,qa2.y, qb1.z,qb1.w, qb2.x,qb2.y)
        }
        // center tap (weight exactly 1): px0 cols 2, px1 col 3
        S1A0 += qa1.x; S0A0 += qa1.y; S1B0 += qb1.x; S0B0 += qb1.y;
        S1A1 += qa1.z; S0A1 += qa1.w; S1B1 += qb1.z; S0B1 += qb1.w;
    }

    int idx = b * HW + gy * W + gx;

    float a1, a0;
    a1 = expf(S1A0); a0 = expf(S0A0);
    float xA0 = fminf(fmaxf(a1 / (1e-6f + (a0 + a1)), 0.1f), 0.9f);
    a1 = expf(S1B0); a0 = expf(S0B0);
    float xB0 = fminf(fmaxf(a1 / (1e-6f + (a0 + a1)), 0.1f), 0.9f);
    a1 = expf(S1A1); a0 = expf(S0A1);
    float xA1 = fminf(fmaxf(a1 / (1e-6f + (a0 + a1)), 0.1f), 0.9f);
    a1 = expf(S1B1); a0 = expf(S0B1);
    float xB1 = fminf(fmaxf(a1 / (1e-6f + (a0 + a1)), 0.1f), 0.9f);

    if (!last) {
        __stcs(&Ld[idx],     make_float4(logf(xA0), logf(1.0f - xA0),
                                         logf(xB0), logf(1.0f - xB0)));
        __stcs(&Ld[idx + 1], make_float4(logf(xA1), logf(1.0f - xA1),
                                         logf(xB1), logf(1.0f - xB1)));
    } else {
        // fused finalize: rgb_mask write + per-batch IoU counting (2 px)
        float2 tg = *(const float2*)&targets[idx];
        float2 sg = *(const float2*)&seg[idx];
        float2 sm = *(const float2*)&sam[idx];
        bool t0 = (tg.x != 0.f), t1 = (tg.y != 0.f);
        bool p00 = (sg.x > 0.5f), p01 = (sg.y > 0.5f);
        bool p10 = (xA0 > 0.5f),  p11 = (xA1 > 0.5f);
        bool p20 = (xB0 > 0.5f),  p21 = (xB1 > 0.5f);
        bool p30 = (sm.x != 0.f), p31 = (sm.y != 0.f);

        float2 om = make_float2(p10 ? 1.f : 0.f, p11 ? 1.f : 0.f);
        __stcs((float2*)&out_mask[idx], om);

        __shared__ unsigned int c[8];
        if (tid < 8) c[tid] = 0u;
        __syncthreads();

        bool pr0[4] = {p00, p10, p20, p30};
        bool pr1[4] = {p01, p11, p21, p31};
        int lane = tid & 31;
        #pragma unroll
        for (int m = 0; m < 4; m++) {
            unsigned bi = __ballot_sync(0xFFFFFFFFu, t0 && pr0[m]);
            unsigned bu = __ballot_sync(0xFFFFFFFFu, t0 || pr0[m]);
            unsigned ci = __ballot_sync(0xFFFFFFFFu, t1 && pr1[m]);
            unsigned cu = __ballot_sync(0xFFFFFFFFu, t1 || pr1[m]);
            if (lane == 0) {
                atomicAdd(&c[2 * m + 0], (unsigned)(__popc(bi) + __popc(ci)));
                atomicAdd(&c[2 * m + 1], (unsigned)(__popc(bu) + __popc(cu)));
            }
        }
        __syncthreads();
        if (tid < 8)
            atomicAdd(&g_cnt[b * 8 + tid], c[tid]);
    }
}

// ---------------------------------------------------------------------------
// Parallel IoU: 64 threads, one (mask m, batch b) pair each.
// ---------------------------------------------------------------------------
__global__ void iou_kernel(float* __restrict__ out_ious) {
    int t = threadIdx.x;              // 0..63
    int m = t >> 4;                   // 0..3
    int b = t & 15;                   // 0..15
    float inter = (float)g_cnt[b * 8 + 2 * m + 0];
    float uni   = (float)g_cnt[b * 8 + 2 * m + 1];
    float v = inter / (uni + 1e-6f);
    #pragma unroll
    for (int off = 8; off > 0; off >>= 1)
        v += __shfl_down_sync(0xFFFFFFFFu, v, off, 16);
    if (b == 0)
        out_ious[m] = v * (1.0f / (float)BATCH);
}

// ---------------------------------------------------------------------------
extern "C" void kernel_launch(void* const* d_in, const int* in_sizes, int n_in,
                              void* d_out, int out_size) {
    const float* fm      = (const float*)d_in[0];  // (16,3,256,256)
    const float* seg     = (const float*)d_in[1];  // (16,256,256)
    const float* depth   = (const float*)d_in[2];
    const float* targets = (const float*)d_in[3];
    const float* sam     = (const float*)d_in[4];
    float* out = (float*)d_out;

    zero_pad<<<BATCH * NPLANE, 256>>>();
    build_kernels<<<dim3(W / BTW, H / TH, BATCH), dim3(BTW, TH)>>>(fm, depth, seg);

    // Two-phase L2-blocked schedule (8 batches x 10 iterations per phase).
    dim3 grd(W / TILEW, H / TH, GB);   // (4, 32, 8) = 1024 blocks of 256
    for (int g = 0; g < BATCH / GB; g++) {
        int src = 0;
        for (int it = 0; it < NITER; it++) {
            mf_iter<<<grd, NT>>>(src, it == NITER - 1, g * GB,
                                 seg, targets, sam, out);
            src ^= 1;
        }
    }

    iou_kernel<<<1, 64>>>(out + (out_size - 4));
}

// round 15
// speedup vs baseline: 1.0678x; 1.0678x over previous
#include <cuda_runtime.h>

#define BATCH 16
#define H 256
#define W 256
#define HW (H*W)
#define NPLANE 12            // unique off-center taps (center weight == 1)
#define RAD 2
#define NITER 10
#define GB 8                 // batches per phase (L2 working set ~51.5 MB)

// padded weight plane: 2 cols left, 2 cols right, 2 rows bottom (zeros)
#define PW 260
#define PH 258
#define PLANE (PW*PH)

// mf_iter tile: 512 threads, 1 px/thread -> 64x8 pixels
#define NT 512
#define TILEW 64
#define TH 8
#define SHW (TILEW + 2*RAD)   // 68
#define SHH (TH + 2*RAD)      // 12

// build tile: 32x8 px
#define BTW 32
#define BHALOW (BTW + 2*RAD)  // 36
#define BHALOH (TH + 2*RAD)   // 12

// Scratch (no cudaMalloc): ~137 MB of __device__ globals.
__device__ float2 g_k[BATCH * NPLANE * PLANE];  // interleaved {kA,kB}, padded
__device__ float4 g_L[2][BATCH * HW];           // {logxA, log1mxA, logxB, log1mxB}
__device__ unsigned int g_cnt[BATCH * 8];

// ---------------------------------------------------------------------------
// Build 12 unique-tap weight plane pairs per batch; fused mean-field init.
// Also fused: border zeroing of this batch's weight planes (by==0 blocks)
// and IoU counter zeroing (block 0,0,0) — disjoint memory, consumed only by
// later launches, so no intra-kernel ordering is needed.
// ---------------------------------------------------------------------------
__global__ __launch_bounds__(256) void build_kernels(
    const float* __restrict__ fm, const float* __restrict__ depth,
    const float* __restrict__ seg) {
    __shared__ float sf0[BHALOH][BHALOW];
    __shared__ float sf1[BHALOH][BHALOW];
    __shared__ float sf2[BHALOH][BHALOW];
    __shared__ float sd [BHALOH][BHALOW];

    int b   = blockIdx.z;
    int ty0 = blockIdx.y * TH;
    int tx0 = blockIdx.x * BTW;
    int tid = threadIdx.y * BTW + threadIdx.x;

    // fused zero_pad: the 8 by==0 blocks of each batch zero that batch's
    // plane borders (12 planes x (2 bottom rows x PW + 4 side cols x 256)).
    if (blockIdx.y == 0) {
        const float2 z = make_float2(0.f, 0.f);
        int worker = blockIdx.x * 256 + tid;          // 0..2047 per batch
        for (int pl = 0; pl < NPLANE; pl++) {
            float2* p = g_k + (size_t)(b * NPLANE + pl) * PLANE;
            for (int i = worker; i < 2 * PW; i += 2048) {
                int r = 256 + i / PW, c = i % PW;
                p[r * PW + c] = z;
            }
            for (int i = worker; i < 256 * 4; i += 2048) {
                int r = i / 4, cc = i % 4;
                int c = (cc < 2) ? cc : (256 + cc);
                p[r * PW + c] = z;
            }
        }
        if (blockIdx.x == 0 && blockIdx.z == 0 && tid < BATCH * 8)
            g_cnt[tid] = 0u;
    }

    for (int i = tid; i < BHALOH * BHALOW; i += TH * BTW) {
        int hy = i / BHALOW, hx = i % BHALOW;
        int gy = ty0 + hy - RAD, gx = tx0 + hx - RAD;
        float f0 = 0.f, f1 = 0.f, f2 = 0.f, d = 0.f;
        if (gy >= 0 && gy < H && gx >= 0 && gx < W) {
            int idx = gy * W + gx;
            f0 = fm[(b * 3 + 0) * HW + idx] + 10.f;
            f1 = fm[(b * 3 + 1) * HW + idx] + 10.f;
            f2 = fm[(b * 3 + 2) * HW + idx] + 10.f;
            d  = depth[b * HW + idx];
        }
        sf0[hy][hx] = f0; sf1[hy][hx] = f1; sf2[hy][hx] = f2; sd[hy][hx] = d;
    }
    __syncthreads();

    int ly = threadIdx.y, lx = threadIdx.x;
    int gy = ty0 + ly, gx = tx0 + lx;

    float c0 = sf0[ly + RAD][lx + RAD];
    float c1 = sf1[ly + RAD][lx + RAD];
    float c2 = sf2[ly + RAD][lx + RAD];
    float cd = sd [ly + RAD][lx + RAD];

    float2* kout = g_k + (size_t)(b * NPLANE) * PLANE + gy * PW + (gx + 2);

    #pragma unroll
    for (int t = 0; t < NPLANE; t++) {
        int kh = t / 5, kw = t % 5;
        float d0 = sf0[ly + kh][lx + kw] - c0;
        float d1 = sf1[ly + kh][lx + kw] - c1;
        float d2 = sf2[ly + kh][lx + kw] - c2;
        float s  = d0 * d0 + d1 * d1 + d2 * d2;
        float k  = expf(-(s / 0.02f));
        float dd = sd[ly + kh][lx + kw] - cd;
        float ks = k * expf(-((dd * dd) / 0.02f));
        kout[(size_t)t * PLANE] = make_float2(k, ks);
    }

    // fused mean-field init: x0 = clip(seg, 0.1, 0.9); store log pair x2
    {
        int idx = b * HW + gy * W + gx;
        float x = fminf(fmaxf(seg[idx], 0.1f), 0.9f);
        float l1 = logf(x), l0 = logf(1.0f - x);
        g_L[0][idx] = make_float4(l1, l0, l1, l0);
    }
}

// ---------------------------------------------------------------------------
// One mean-field iteration, both chains packed in float4, 1 px/thread,
// 512-thread blocks, 4 blocks/SM (32-reg cap -> ~100% theoretical occ):
//   S(p) = L(p) + sum_t [ w_t(p) * L(p+o_t) + w_t(p-o_t) * L(p-o_t) ]
// GB=8 phase per launch (weights L2-resident across the phase's 10 iters).
// Last iteration fuses mask write + IoU counting. (Exact round-13 body.)
// ---------------------------------------------------------------------------
__global__ __launch_bounds__(NT, 4) void mf_iter(
    int src, int last, int b0,
    const float* __restrict__ seg, const float* __restrict__ targets,
    const float* __restrict__ sam, float* __restrict__ out_mask) {
    __shared__ float4 sb[SHH][SHW];   // {logxA, log1mxA, logxB, log1mxB}

    int b   = b0 + blockIdx.z;
    int ty0 = blockIdx.y * TH;
    int tx0 = blockIdx.x * TILEW;
    int tid = threadIdx.x;

    const float4* __restrict__ Ls = g_L[src];
    float4* Ld = g_L[src ^ 1];

    #pragma unroll
    for (int i = tid; i < SHH * SHW; i += NT) {
        int hy = i / SHW, hx = i % SHW;
        int gy = ty0 + hy - RAD, gx = tx0 + hx - RAD;
        float4 v = make_float4(0.f, 0.f, 0.f, 0.f);
        if ((unsigned)gy < H && (unsigned)gx < W)
            v = __ldcs(&Ls[b * HW + gy * W + gx]);
        sb[hy][hx] = v;
    }
    __syncthreads();

    int lx = tid & (TILEW - 1);       // 0..63, lanes consecutive in x
    int ly = tid >> 6;                // 0..7
    int gy = ty0 + ly, gx = tx0 + lx;

    const float2* __restrict__ kp =
        g_k + (size_t)(b * NPLANE) * PLANE + gy * PW + (gx + 2);

    float S1A = 0.f, S0A = 0.f, S1B = 0.f, S0B = 0.f;

    #pragma unroll
    for (int t = 0; t < NPLANE; t++) {
        const int kh = t / 5, kw = t % 5;
        const int moff = (2 - kh) * PW + (2 - kw);   // mirror weight offset
        float2 wf = __ldg(kp + (size_t)t * PLANE);
        float2 wm = __ldg(kp + (size_t)t * PLANE + moff);

        float4 f = sb[ly + kh][lx + kw];
        float4 m = sb[ly + 4 - kh][lx + 4 - kw];

        S1A += wf.x * f.x + wm.x * m.x;
        S0A += wf.x * f.y + wm.x * m.y;
        S1B += wf.y * f.z + wm.y * m.z;
        S0B += wf.y * f.w + wm.y * m.w;
    }
    // center tap: weight exactly 1
    {
        float4 c = sb[ly + 2][lx + 2];
        S1A += c.x; S0A += c.y; S1B += c.z; S0B += c.w;
    }

    int idx = b * HW + gy * W + gx;

    float a1, a0;
    a1 = expf(S1A); a0 = expf(S0A);
    float xA = fminf(fmaxf(a1 / (1e-6f + (a0 + a1)), 0.1f), 0.9f);
    a1 = expf(S1B); a0 = expf(S0B);
    float xB = fminf(fmaxf(a1 / (1e-6f + (a0 + a1)), 0.1f), 0.9f);

    if (!last) {
        __stcs(&Ld[idx], make_float4(logf(xA), logf(1.0f - xA),
                                     logf(xB), logf(1.0f - xB)));
    } else {
        // fused finalize: rgb_mask write + per-batch IoU counting
        bool t0 = (targets[idx] != 0.f);
        bool p0 = (seg[idx]  > 0.5f);
        bool p1 = (xA > 0.5f);
        bool p2 = (xB > 0.5f);
        bool p3 = (sam[idx] != 0.f);

        __stcs(&out_mask[idx], p1 ? 1.f : 0.f);

        __shared__ unsigned int c[8];
        if (tid < 8) c[tid] = 0u;
        __syncthreads();

        bool pr[4] = {p0, p1, p2, p3};
        int lane = tid & 31;
        #pragma unroll
        for (int m = 0; m < 4; m++) {
            unsigned bi = __ballot_sync(0xFFFFFFFFu, t0 && pr[m]);
            unsigned bu = __ballot_sync(0xFFFFFFFFu, t0 || pr[m]);
            if (lane == 0) {
                atomicAdd(&c[2 * m + 0], (unsigned)__popc(bi));
                atomicAdd(&c[2 * m + 1], (unsigned)__popc(bu));
            }
        }
        __syncthreads();
        if (tid < 8)
            atomicAdd(&g_cnt[b * 8 + tid], c[tid]);
    }
}

// ---------------------------------------------------------------------------
// Parallel IoU: 64 threads, one (mask m, batch b) pair each; 16-lane
// segmented shuffle reduction over batches.
// ---------------------------------------------------------------------------
__global__ void iou_kernel(float* __restrict__ out_ious) {
    int t = threadIdx.x;              // 0..63
    int m = t >> 4;                   // 0..3
    int b = t & 15;                   // 0..15
    float inter = (float)g_cnt[b * 8 + 2 * m + 0];
    float uni   = (float)g_cnt[b * 8 + 2 * m + 1];
    float v = inter / (uni + 1e-6f);
    #pragma unroll
    for (int off = 8; off > 0; off >>= 1)
        v += __shfl_down_sync(0xFFFFFFFFu, v, off, 16);
    if (b == 0)
        out_ious[m] = v * (1.0f / (float)BATCH);
}

// ---------------------------------------------------------------------------
extern "C" void kernel_launch(void* const* d_in, const int* in_sizes, int n_in,
                              void* d_out, int out_size) {
    const float* fm      = (const float*)d_in[0];  // (16,3,256,256)
    const float* seg     = (const float*)d_in[1];  // (16,256,256)
    const float* depth   = (const float*)d_in[2];
    const float* targets = (const float*)d_in[3];
    const float* sam     = (const float*)d_in[4];
    float* out = (float*)d_out;

    build_kernels<<<dim3(W / BTW, H / TH, BATCH), dim3(BTW, TH)>>>(fm, depth, seg);

    // Two-phase L2-blocked schedule (8 batches x 10 iterations per phase).
    dim3 grd(W / TILEW, H / TH, GB);   // (4, 32, 8) = 1024 blocks
    for (int g = 0; g < BATCH / GB; g++) {
        int src = 0;
        for (int it = 0; it < NITER; it++) {
            mf_iter<<<grd, NT>>>(src, it == NITER - 1, g * GB,
                                 seg, targets, sam, out);
            src ^= 1;
        }
    }

    iou_kernel<<<1, 64>>>(out + (out_size - 4));
}